// round 15
// baseline (speedup 1.0000x reference)
#include <cuda_runtime.h>
#include <cstdint>

#define BB        32
#define DIMS      8
#define DEG       32
#define P         2
#define TPB       256
#define TILE_POS  (TPB * P)        // 512 positions per tile
#define GRIDX     592              // 148 SM x 4 CTA -> single wave
#define ZBUF_BYTES 4096

__device__ __forceinline__ float ex2f(float x) {
    float r; asm("ex2.approx.f32 %0, %1;" : "=f"(r) : "f"(x)); return r;
}
__device__ __forceinline__ unsigned long long pack2(float lo, float hi) {
    unsigned long long r;
    asm("mov.b64 %0, {%1, %2};" : "=l"(r) : "f"(lo), "f"(hi)); return r;
}
__device__ __forceinline__ void unpack2(unsigned long long v, float& lo, float& hi) {
    asm("mov.b64 {%0, %1}, %2;" : "=f"(lo), "=f"(hi) : "l"(v));
}
__device__ __forceinline__ unsigned long long fma2(unsigned long long a,
                                                   unsigned long long b,
                                                   unsigned long long c) {
    unsigned long long r;
    asm("fma.rn.f32x2 %0, %1, %2, %3;" : "=l"(r) : "l"(a), "l"(b), "l"(c));
    return r;
}
__device__ __forceinline__ unsigned long long mul2(unsigned long long a,
                                                   unsigned long long b) {
    unsigned long long r;
    asm("mul.rn.f32x2 %0, %1, %2;" : "=l"(r) : "l"(a), "l"(b));
    return r;
}
__device__ __forceinline__ uint32_t smem_u32(const void* p) {
    uint32_t a;
    asm("{ .reg .u64 t; cvta.to.shared.u64 t, %1; cvt.u32.u64 %0, t; }"
        : "=r"(a) : "l"(p));
    return a;
}
// 256-bit dense store: 8 fp32 = 32B per lane, warp = 1KB contiguous
__device__ __forceinline__ void stg256(float* p,
                                       unsigned long long a0, unsigned long long a1,
                                       unsigned long long a2, unsigned long long a3) {
    float f0, f1, f2, f3, f4, f5, f6, f7;
    unpack2(a0, f0, f1); unpack2(a1, f2, f3);
    unpack2(a2, f4, f5); unpack2(a3, f6, f7);
    asm volatile("st.global.v8.f32 [%0], {%1,%2,%3,%4,%5,%6,%7,%8};"
                 :: "l"(p), "f"(f0), "f"(f1), "f"(f2), "f"(f3),
                    "f"(f4), "f"(f5), "f"(f6), "f"(f7)
                 : "memory");
}

__global__ __launch_bounds__(TPB, 4) void basis_kernel(
    const float* __restrict__ weights,    // (B, DIMS, DEG)
    const float* __restrict__ positions,  // (B, N)
    float* __restrict__ out,              // (B, N, DIMS) [+ zeros half]
    int N, int write_zeros)
{
    // sw2[g*4 + dp] = (w'[2dp][g], w'[2dp+1][g]) with w' = w * c_g pre-folded
    __shared__ __align__(16) unsigned long long sw2[DEG * 4];
    __shared__ __align__(16) float zbuf[ZBUF_BYTES / 4];   // stays zero

    const int tid  = threadIdx.x;
    const int lane = tid & 31;
    const int wrp  = tid >> 5;
    const int cta  = blockIdx.x;

    const int tiles_per_b = N / TILE_POS;             // 128
    const int tot_tiles   = BB * tiles_per_b;         // 4096
    const size_t R = (size_t)BB * (size_t)N * DIMS;   // zeros-half offset

    // Balanced contiguous static partition of tiles over GRIDX CTAs
    const int q = tot_tiles / GRIDX;                  // 6
    const int r = tot_tiles % GRIDX;                  // 544
    int start, cnt;
    if (cta < r) { cnt = q + 1; start = cta * (q + 1); }
    else         { cnt = q;     start = r * (q + 1) + (cta - r) * q; }

    const float s = 1.01f / 31.0f;
    const float L = 12.5f * 1.4426950408889634f;

    // Zero staging buffer once (1 STS.128/thread); never rewritten
    {
        const float4 z = {0.0f, 0.0f, 0.0f, 0.0f};
        reinterpret_cast<float4*>(zbuf)[tid] = z;
    }
    // precompute this thread's weight-slot indices (tid = g*8 + d)
    const int wg = tid >> 3;
    const int wd = tid & 7;
    const float cg = ex2f(-L * s * s * (float)(wg * wg));

    int bprev = -1;

    for (int i = 0; i < cnt; i++) {
        const int t = start + i;
        const int b = t / tiles_per_b;
        const int chunk = t - b * tiles_per_b;

        if (b != bprev) {
            __syncthreads();   // all warps done reading old weights
            reinterpret_cast<float*>(sw2)[tid] =
                weights[b * DIMS * DEG + wd * DEG + wg] * cg;
            __syncthreads();   // new weights + (iter 0) zbuf visible
            bprev = b;
        }

        const int nblk = chunk * TILE_POS;
        const int nwarp = nblk + wrp * (32 * P);
        const float* pp = positions + (size_t)b * N + nwarp;
        const size_t basew = ((size_t)b * N + nwarp) * DIMS;

        // Zeros half for this tile (16KB) via bulk async stores, overlapped
        if (write_zeros && tid == 0) {
            asm volatile("fence.proxy.async.shared::cta;" ::: "memory");
            float* zdst = out + R + ((size_t)b * N + nblk) * DIMS;
            const uint32_t src = smem_u32(zbuf);
#pragma unroll
            for (int j = 0; j < 4; j++) {
                asm volatile(
                    "cp.async.bulk.global.shared::cta.bulk_group [%0], [%1], %2;"
                    :: "l"(zdst + j * (ZBUF_BYTES / 4)), "r"(src), "n"(ZBUF_BYTES)
                    : "memory");
            }
            asm volatile("cp.async.bulk.commit_group;" ::: "memory");
        }

        // Coalesced position loads (stride-32 interleave within warp's 64)
        float x[P];
#pragma unroll
        for (int p = 0; p < P; p++)
            x[p] = pp[lane + 32 * p];

        // e_g = e_0 * q^g * c_g :  e_0 = 2^(-L x^2),  q = 2^(2 L s x)
        unsigned long long eD[P], qD[P];
#pragma unroll
        for (int p = 0; p < P; p++) {
            const float e0 = ex2f(-L * x[p] * x[p]);
            const float qq = ex2f(2.0f * L * s * x[p]);
            eD[p] = pack2(e0, e0);
            qD[p] = pack2(qq, qq);
        }

        unsigned long long acc[P][4];
#pragma unroll
        for (int p = 0; p < P; p++)
#pragma unroll
            for (int dp = 0; dp < 4; dp++)
                acc[p][dp] = 0ull;

#pragma unroll
        for (int g = 0; g < DEG; g++) {
            const ulonglong2 w01 = *reinterpret_cast<const ulonglong2*>(sw2 + g * 4);
            const ulonglong2 w23 = *reinterpret_cast<const ulonglong2*>(sw2 + g * 4 + 2);
#pragma unroll
            for (int p = 0; p < P; p++) {
                acc[p][0] = fma2(eD[p], w01.x, acc[p][0]);
                acc[p][1] = fma2(eD[p], w01.y, acc[p][1]);
                acc[p][2] = fma2(eD[p], w23.x, acc[p][2]);
                acc[p][3] = fma2(eD[p], w23.y, acc[p][3]);
                eD[p] = mul2(eD[p], qD[p]);
            }
        }

        // Dense 256-bit stores: warp writes 1KB contiguous per instruction
#pragma unroll
        for (int p = 0; p < P; p++) {
            float* o = out + basew + (size_t)(32 * p + lane) * DIMS;
            stg256(o, acc[p][0], acc[p][1], acc[p][2], acc[p][3]);
        }
    }

    if (write_zeros && tid == 0) {
        asm volatile("cp.async.bulk.wait_group 0;" ::: "memory");
    }
}

extern "C" void kernel_launch(void* const* d_in, const int* in_sizes, int n_in,
                              void* d_out, int out_size)
{
    const float* weights   = (const float*)d_in[0];
    const float* positions = (const float*)d_in[2];
    float* out = (float*)d_out;

    const int N = in_sizes[2] / BB;                 // 65536
    const long long R = (long long)BB * N * DIMS;
    const int write_zeros = (out_size >= 2 * R) ? 1 : 0;

    basis_kernel<<<GRIDX, TPB>>>(weights, positions, out, N, write_zeros);
}

// round 16
// speedup vs baseline: 1.1534x; 1.1534x over previous
#include <cuda_runtime.h>
#include <cstdint>

#define BB    32
#define DIMS  8
#define DEG   32
#define P     2
#define TPB   256
#define ZBUF_BYTES 4096

__device__ __forceinline__ float ex2f(float x) {
    float r; asm("ex2.approx.f32 %0, %1;" : "=f"(r) : "f"(x)); return r;
}
__device__ __forceinline__ unsigned long long pack2(float lo, float hi) {
    unsigned long long r;
    asm("mov.b64 %0, {%1, %2};" : "=l"(r) : "f"(lo), "f"(hi)); return r;
}
__device__ __forceinline__ void unpack2(unsigned long long v, float& lo, float& hi) {
    asm("mov.b64 {%0, %1}, %2;" : "=f"(lo), "=f"(hi) : "l"(v));
}
__device__ __forceinline__ unsigned long long fma2(unsigned long long a,
                                                   unsigned long long b,
                                                   unsigned long long c) {
    unsigned long long r;
    asm("fma.rn.f32x2 %0, %1, %2, %3;" : "=l"(r) : "l"(a), "l"(b), "l"(c));
    return r;
}
__device__ __forceinline__ unsigned long long mul2(unsigned long long a,
                                                   unsigned long long b) {
    unsigned long long r;
    asm("mul.rn.f32x2 %0, %1, %2;" : "=l"(r) : "l"(a), "l"(b));
    return r;
}
__device__ __forceinline__ uint32_t smem_u32(const void* p) {
    uint32_t a;
    asm("{ .reg .u64 t; cvta.to.shared.u64 t, %1; cvt.u32.u64 %0, t; }"
        : "=r"(a) : "l"(p));
    return a;
}
// 256-bit dense store: 8 fp32 = 32B per lane, warp = 1KB contiguous
__device__ __forceinline__ void stg256(float* p,
                                       unsigned long long a0, unsigned long long a1,
                                       unsigned long long a2, unsigned long long a3) {
    float f0, f1, f2, f3, f4, f5, f6, f7;
    unpack2(a0, f0, f1); unpack2(a1, f2, f3);
    unpack2(a2, f4, f5); unpack2(a3, f6, f7);
    asm volatile("st.global.v8.f32 [%0], {%1,%2,%3,%4,%5,%6,%7,%8};"
                 :: "l"(p), "f"(f0), "f"(f1), "f"(f2), "f"(f3),
                    "f"(f4), "f"(f5), "f"(f6), "f"(f7)
                 : "memory");
}

__global__ __launch_bounds__(TPB, 5) void basis_kernel(
    const float* __restrict__ weights,    // (B, DIMS, DEG)
    const float* __restrict__ positions,  // (B, N)
    float* __restrict__ out,              // (B, N, DIMS) [+ zeros half]
    int N, int write_zeros)
{
    // sw2[g*4 + dp] = (w'[2dp][g], w'[2dp+1][g]) with w' = w * c_g pre-folded
    __shared__ __align__(16) unsigned long long sw2[DEG * 4];
    __shared__ __align__(16) float zbuf[ZBUF_BYTES / 4];   // stays zero

    const int b    = blockIdx.y;
    const int tid  = threadIdx.x;
    const int lane = tid & 31;
    const int wrp  = tid >> 5;

    const int nblk  = blockIdx.x * (TPB * P);     // 512 positions per block
    const int nwarp = nblk + wrp * (32 * P);      // 64 per warp
    const float* pp = positions + (size_t)b * N + nwarp;
    const size_t basew = ((size_t)b * N + nwarp) * DIMS;

    const float s = 1.01f / 31.0f;
    const float L = 12.5f * 1.4426950408889634f;

    // Zero the smem staging buffer (1 STS.128/thread)
    {
        const float4 z = {0.0f, 0.0f, 0.0f, 0.0f};
        reinterpret_cast<float4*>(zbuf)[tid] = z;
    }
    {
        // float view index = g*8 + d == tid; fold c_g = 2^(-L s^2 g^2) into w
        const int g = tid >> 3;
        const int d = tid & 7;
        const float cg = ex2f(-L * s * s * (float)(g * g));
        reinterpret_cast<float*>(sw2)[tid] = weights[b * DIMS * DEG + d * DEG + g] * cg;
    }
    __syncthreads();

    // Zeros half via bulk async stores (16KB block span), overlapped with compute
    if (write_zeros && tid == 0) {
        asm volatile("fence.proxy.async.shared::cta;" ::: "memory");
        const size_t R = (size_t)gridDim.y * (size_t)N * DIMS;
        float* zdst = out + R + ((size_t)b * N + nblk) * DIMS;
        const uint32_t src = smem_u32(zbuf);
#pragma unroll
        for (int i = 0; i < 4; i++) {
            asm volatile(
                "cp.async.bulk.global.shared::cta.bulk_group [%0], [%1], %2;"
                :: "l"(zdst + i * (ZBUF_BYTES / 4)), "r"(src), "n"(ZBUF_BYTES)
                : "memory");
        }
        asm volatile("cp.async.bulk.commit_group;" ::: "memory");
    }

    // Coalesced position loads (stride-32 interleave within the warp's 64)
    float x[P];
#pragma unroll
    for (int p = 0; p < P; p++)
        x[p] = pp[lane + 32 * p];

    // Horner form: res_d = e0 * P_d(q),  P_d(q) = sum_g w'_{d,g} q^g
    //   e0 = 2^(-L x^2),  q = 2^(2 L s x)
    unsigned long long e0D[P], qD[P];
#pragma unroll
    for (int p = 0; p < P; p++) {
        const float e0 = ex2f(-L * x[p] * x[p]);
        const float q  = ex2f(2.0f * L * s * x[p]);
        e0D[p] = pack2(e0, e0);
        qD[p]  = pack2(q, q);
    }

    unsigned long long acc[P][4];
#pragma unroll
    for (int p = 0; p < P; p++)
#pragma unroll
        for (int dp = 0; dp < 4; dp++)
            acc[p][dp] = 0ull;

    // Horner: g = 31 .. 0,  acc = acc*q + w'_g   (no separate recurrence mul)
#pragma unroll
    for (int g = DEG - 1; g >= 0; g--) {
        const ulonglong2 w01 = *reinterpret_cast<const ulonglong2*>(sw2 + g * 4);
        const ulonglong2 w23 = *reinterpret_cast<const ulonglong2*>(sw2 + g * 4 + 2);
#pragma unroll
        for (int p = 0; p < P; p++) {
            acc[p][0] = fma2(acc[p][0], qD[p], w01.x);
            acc[p][1] = fma2(acc[p][1], qD[p], w01.y);
            acc[p][2] = fma2(acc[p][2], qD[p], w23.x);
            acc[p][3] = fma2(acc[p][3], qD[p], w23.y);
        }
    }

    // Epilogue scale + dense 256-bit stores (warp writes 1KB per instruction)
#pragma unroll
    for (int p = 0; p < P; p++) {
        float* o = out + basew + (size_t)(32 * p + lane) * DIMS;
        stg256(o,
               mul2(acc[p][0], e0D[p]), mul2(acc[p][1], e0D[p]),
               mul2(acc[p][2], e0D[p]), mul2(acc[p][3], e0D[p]));
    }

    if (write_zeros && tid == 0) {
        asm volatile("cp.async.bulk.wait_group 0;" ::: "memory");
    }
}

extern "C" void kernel_launch(void* const* d_in, const int* in_sizes, int n_in,
                              void* d_out, int out_size)
{
    const float* weights   = (const float*)d_in[0];
    const float* positions = (const float*)d_in[2];
    float* out = (float*)d_out;

    const int N = in_sizes[2] / BB;                 // 65536
    const long long R = (long long)BB * N * DIMS;
    const int write_zeros = (out_size >= 2 * R) ? 1 : 0;

    dim3 grid(N / (TPB * P), BB);                   // (128, 32)
    basis_kernel<<<grid, TPB>>>(weights, positions, out, N, write_zeros);
}

// round 17
// speedup vs baseline: 1.2264x; 1.0633x over previous
#include <cuda_runtime.h>
#include <cstdint>

#define BB    32
#define DIMS  8
#define DEG   32
#define P     4
#define TPB   256
#define ZBUF_BYTES 4096

__device__ __forceinline__ float ex2f(float x) {
    float r; asm("ex2.approx.f32 %0, %1;" : "=f"(r) : "f"(x)); return r;
}
__device__ __forceinline__ unsigned long long pack2(float lo, float hi) {
    unsigned long long r;
    asm("mov.b64 %0, {%1, %2};" : "=l"(r) : "f"(lo), "f"(hi)); return r;
}
__device__ __forceinline__ void unpack2(unsigned long long v, float& lo, float& hi) {
    asm("mov.b64 {%0, %1}, %2;" : "=f"(lo), "=f"(hi) : "l"(v));
}
__device__ __forceinline__ unsigned long long fma2(unsigned long long a,
                                                   unsigned long long b,
                                                   unsigned long long c) {
    unsigned long long r;
    asm("fma.rn.f32x2 %0, %1, %2, %3;" : "=l"(r) : "l"(a), "l"(b), "l"(c));
    return r;
}
__device__ __forceinline__ unsigned long long mul2(unsigned long long a,
                                                   unsigned long long b) {
    unsigned long long r;
    asm("mul.rn.f32x2 %0, %1, %2;" : "=l"(r) : "l"(a), "l"(b));
    return r;
}
__device__ __forceinline__ uint32_t smem_u32(const void* p) {
    uint32_t a;
    asm("{ .reg .u64 t; cvta.to.shared.u64 t, %1; cvt.u32.u64 %0, t; }"
        : "=r"(a) : "l"(p));
    return a;
}
// 256-bit dense store: 8 fp32 = 32B per lane, warp = 1KB contiguous
__device__ __forceinline__ void stg256(float* p,
                                       unsigned long long a0, unsigned long long a1,
                                       unsigned long long a2, unsigned long long a3) {
    float f0, f1, f2, f3, f4, f5, f6, f7;
    unpack2(a0, f0, f1); unpack2(a1, f2, f3);
    unpack2(a2, f4, f5); unpack2(a3, f6, f7);
    asm volatile("st.global.v8.f32 [%0], {%1,%2,%3,%4,%5,%6,%7,%8};"
                 :: "l"(p), "f"(f0), "f"(f1), "f"(f2), "f"(f3),
                    "f"(f4), "f"(f5), "f"(f6), "f"(f7)
                 : "memory");
}

__global__ __launch_bounds__(TPB, 4) void basis_kernel(
    const float* __restrict__ weights,    // (B, DIMS, DEG)
    const float* __restrict__ positions,  // (B, N)
    float* __restrict__ out,              // (B, N, DIMS) [+ zeros half]
    int N, int write_zeros)
{
    // sw2[g*4 + dp] = (w'[2dp][g], w'[2dp+1][g]) with w' = w * c_g pre-folded
    __shared__ __align__(16) unsigned long long sw2[DEG * 4];
    __shared__ __align__(16) float zbuf[ZBUF_BYTES / 4];   // stays zero

    const int b    = blockIdx.y;
    const int tid  = threadIdx.x;
    const int lane = tid & 31;
    const int wrp  = tid >> 5;

    const int nblk  = blockIdx.x * (TPB * P);     // 1024 positions per block
    const int nwarp = nblk + wrp * (32 * P);      // 128 per warp
    const float* pp = positions + (size_t)b * N + nwarp;
    const size_t basew = ((size_t)b * N + nwarp) * DIMS;

    const float s = 1.01f / 31.0f;
    const float L = 12.5f * 1.4426950408889634f;

    // Zero the smem staging buffer (1 STS.128/thread)
    {
        const float4 z = {0.0f, 0.0f, 0.0f, 0.0f};
        reinterpret_cast<float4*>(zbuf)[tid] = z;
    }
    {
        // float view index = g*8 + d == tid; fold c_g = 2^(-L s^2 g^2) into w
        const int g = tid >> 3;
        const int d = tid & 7;
        const float cg = ex2f(-L * s * s * (float)(g * g));
        reinterpret_cast<float*>(sw2)[tid] = weights[b * DIMS * DEG + d * DEG + g] * cg;
    }
    __syncthreads();

    // Zeros half via bulk async stores (32KB block span -> 8 x 4KB), overlapped
    if (write_zeros && tid == 0) {
        asm volatile("fence.proxy.async.shared::cta;" ::: "memory");
        const size_t R = (size_t)gridDim.y * (size_t)N * DIMS;
        float* zdst = out + R + ((size_t)b * N + nblk) * DIMS;
        const uint32_t src = smem_u32(zbuf);
#pragma unroll
        for (int i = 0; i < 8; i++) {
            asm volatile(
                "cp.async.bulk.global.shared::cta.bulk_group [%0], [%1], %2;"
                :: "l"(zdst + i * (ZBUF_BYTES / 4)), "r"(src), "n"(ZBUF_BYTES)
                : "memory");
        }
        asm volatile("cp.async.bulk.commit_group;" ::: "memory");
    }

    // Coalesced position loads (stride-32 interleave within the warp's 128)
    float x[P];
#pragma unroll
    for (int p = 0; p < P; p++)
        x[p] = pp[lane + 32 * p];

    // Horner form: res_d = e0 * P_d(q),  P_d(q) = sum_g w'_{d,g} q^g
    unsigned long long e0D[P], qD[P];
#pragma unroll
    for (int p = 0; p < P; p++) {
        const float e0 = ex2f(-L * x[p] * x[p]);
        const float q  = ex2f(2.0f * L * s * x[p]);
        e0D[p] = pack2(e0, e0);
        qD[p]  = pack2(q, q);
    }

    unsigned long long acc[P][4];
#pragma unroll
    for (int p = 0; p < P; p++)
#pragma unroll
        for (int dp = 0; dp < 4; dp++)
            acc[p][dp] = 0ull;

    // Horner: g = 31 .. 0,  acc = acc*q + w'_g
#pragma unroll
    for (int g = DEG - 1; g >= 0; g--) {
        const ulonglong2 w01 = *reinterpret_cast<const ulonglong2*>(sw2 + g * 4);
        const ulonglong2 w23 = *reinterpret_cast<const ulonglong2*>(sw2 + g * 4 + 2);
#pragma unroll
        for (int p = 0; p < P; p++) {
            acc[p][0] = fma2(acc[p][0], qD[p], w01.x);
            acc[p][1] = fma2(acc[p][1], qD[p], w01.y);
            acc[p][2] = fma2(acc[p][2], qD[p], w23.x);
            acc[p][3] = fma2(acc[p][3], qD[p], w23.y);
        }
    }

    // Epilogue scale + dense 256-bit stores (warp writes 1KB per instruction)
#pragma unroll
    for (int p = 0; p < P; p++) {
        float* o = out + basew + (size_t)(32 * p + lane) * DIMS;
        stg256(o,
               mul2(acc[p][0], e0D[p]), mul2(acc[p][1], e0D[p]),
               mul2(acc[p][2], e0D[p]), mul2(acc[p][3], e0D[p]));
    }

    if (write_zeros && tid == 0) {
        asm volatile("cp.async.bulk.wait_group 0;" ::: "memory");
    }
}

extern "C" void kernel_launch(void* const* d_in, const int* in_sizes, int n_in,
                              void* d_out, int out_size)
{
    const float* weights   = (const float*)d_in[0];
    const float* positions = (const float*)d_in[2];
    float* out = (float*)d_out;

    const int N = in_sizes[2] / BB;                 // 65536
    const long long R = (long long)BB * N * DIMS;
    const int write_zeros = (out_size >= 2 * R) ? 1 : 0;

    dim3 grid(N / (TPB * P), BB);                   // (64, 32)
    basis_kernel<<<grid, TPB>>>(weights, positions, out, N, write_zeros);
}